// round 9
// baseline (speedup 1.0000x reference)
#include <cuda_runtime.h>

// Problem constants (from reference):
//   spikes: (8, 600, 30000) f32; window t in [0, 500)
//   50 samples, up to 200 ids each, prefix mask (count in [15,200])
//   16 fano bin sizes, output = 10 * mse (scalar f32)
// NOTE: sample_ids is declared int64 in the reference but JAX demotes to
// int32 unless x64 is enabled -> detect the real dtype at runtime.
#define NS      50
#define MAXC    200
#define TQ      500        // T_END - T_START
#define NT_TOT  600
#define NN      30000
#define NBINS   16
#define JSPLIT  4          // split id-list 4 ways -> 4 partial sel buffers
#define TCH     2          // t-chunks per sample
#define TPC     250        // timesteps per chunk (500/2)
#define EPS_D   1e-7

__device__ int    g_ids[NS * MAXC];          // ids converted to int32
__device__ int    g_cnt[NS];                 // per-sample valid prefix count
__device__ float  g_part[JSPLIT][NS * TQ];   // partial gather sums (each elem written once)
__device__ float  g_sel[NS * TQ];            // sel[s][t]
__device__ double g_fano_sum[NBINS];         // per-bin sum of fano over samples

// BIN_MS = round(1000 * logspace(-3,0,20)) for b < 0.25  -> 16 bins
__constant__ int c_bins[NBINS] = {1, 1, 2, 3, 4, 6, 9, 13, 18, 26, 38, 55, 78, 113, 162, 234};

// ---------------------------------------------------------------------------
// Kernel 0: detect id dtype (i32 vs i64), convert to int32, compute counts.
// Single block; trivial cost. Detection: interpret buffer as i64 and test 8
// words against [0, NN). True-i64 ids always pass; i32 data packed two-per-
// word has a nonzero high half w.p. ~1, so any out-of-range word => i32.
// Deterministic for fixed inputs.
// ---------------------------------------------------------------------------
__global__ void prep_kernel(const void* __restrict__ ids_raw,
                            const float* __restrict__ mask)
{
    __shared__ int s_is64;
    const int tid = threadIdx.x;

    if (tid == 0) {
        const long long* p64 = (const long long*)ids_raw;
        int is64 = 1;
        #pragma unroll
        for (int k = 0; k < 8; k++) {
            long long v = p64[k];
            if (v < 0 || v >= NN) is64 = 0;
        }
        s_is64 = is64;
    }
    __syncthreads();

    if (s_is64) {
        const long long* p64 = (const long long*)ids_raw;
        for (int i = tid; i < NS * MAXC; i += blockDim.x)
            g_ids[i] = (int)p64[i];
    } else {
        const int* p32 = (const int*)ids_raw;
        for (int i = tid; i < NS * MAXC; i += blockDim.x)
            g_ids[i] = p32[i];
    }

    // per-sample prefix counts (one thread per sample; fixed order)
    if (tid < NS) {
        int c = 0;
        for (int j = 0; j < MAXC; j++)
            if (mask[tid * MAXC + j] > 0.5f) c++;
        g_cnt[tid] = c;
    }
}

// ---------------------------------------------------------------------------
// Kernel 1: gather-sum. grid = (sample, t-chunk, j-split), block = 256.
// Threads 0..199 stage the id list into shared (coalesced); threads 0..249
// each own one timestep and loop over their j-slice of the prefix-valid id
// list with 8 independent accumulators for memory-level parallelism.
// ---------------------------------------------------------------------------
__global__ void gather_kernel(const float* __restrict__ spikes,
                              const int* __restrict__ trials)
{
    __shared__ int sid[MAXC];

    const int s   = blockIdx.x;
    const int tid = threadIdx.x;

    if (tid < MAXC) sid[tid] = g_ids[s * MAXC + tid];
    __syncthreads();

    const int cnt  = g_cnt[s];              // mask is a prefix: valid ids are [0, cnt)
    const int jlen = (cnt + JSPLIT - 1) / JSPLIT;
    const int j0   = blockIdx.z * jlen;
    const int j1   = min(cnt, j0 + jlen);

    if (tid >= TPC) return;
    const int t     = blockIdx.y * TPC + tid;
    const int trial = trials[s];
    const float* __restrict__ p =
        spikes + (size_t)trial * NT_TOT * NN + (size_t)t * NN;

    float a0 = 0.f, a1 = 0.f, a2 = 0.f, a3 = 0.f;
    float a4 = 0.f, a5 = 0.f, a6 = 0.f, a7 = 0.f;
    int j = j0;
    for (; j + 8 <= j1; j += 8) {
        a0 += __ldg(p + sid[j + 0]);
        a1 += __ldg(p + sid[j + 1]);
        a2 += __ldg(p + sid[j + 2]);
        a3 += __ldg(p + sid[j + 3]);
        a4 += __ldg(p + sid[j + 4]);
        a5 += __ldg(p + sid[j + 5]);
        a6 += __ldg(p + sid[j + 6]);
        a7 += __ldg(p + sid[j + 7]);
    }
    for (; j < j1; j++) a0 += __ldg(p + sid[j]);

    g_part[blockIdx.z][s * TQ + t] = ((a0 + a1) + (a2 + a3)) + ((a4 + a5) + (a6 + a7));
}

// ---------------------------------------------------------------------------
// Kernel 2: reduce the JSPLIT partial buffers into g_sel (fixed add order).
// ---------------------------------------------------------------------------
__global__ void reduce_kernel()
{
    int i = blockIdx.x * blockDim.x + threadIdx.x;
    if (i < NS * TQ) {
        g_sel[i] = (g_part[0][i] + g_part[1][i]) + (g_part[2][i] + g_part[3][i]);
    }
}

// ---------------------------------------------------------------------------
// Kernel 3: per-bin fano. grid = 16 bins, block = 8 warps.
// Each warp handles samples s = warp, warp+8, ... ; lanes stripe the nb bins.
// Double accumulators avoid E[x^2]-E[x]^2 cancellation at large bin sizes.
// ---------------------------------------------------------------------------
__global__ void fano_kernel()
{
    const int b    = blockIdx.x;
    const int bs   = c_bins[b];
    const int nb   = TQ / bs;           // floor division, matches reference
    const int warp = threadIdx.x >> 5;
    const int lane = threadIdx.x & 31;
    const int NW   = 8;                 // blockDim.x / 32

    __shared__ double w_sum[NW];

    double fano_acc = 0.0;
    for (int s = warp; s < NS; s += NW) {
        const float* __restrict__ row = g_sel + s * TQ;
        double sum = 0.0, sumsq = 0.0;
        for (int i = lane; i < nb; i += 32) {
            float c = 0.f;
            const int base = i * bs;
            for (int k = 0; k < bs; k++) c += row[base + k];
            sum   += (double)c;
            sumsq += (double)c * (double)c;
        }
        #pragma unroll
        for (int off = 16; off; off >>= 1) {
            sum   += __shfl_down_sync(0xffffffffu, sum,   off);
            sumsq += __shfl_down_sync(0xffffffffu, sumsq, off);
        }
        if (lane == 0) {
            double mean = sum / (double)nb;
            double var  = sumsq / (double)nb - mean * mean;
            double m    = mean > EPS_D ? mean : EPS_D;
            fano_acc += var / m;
        }
    }
    if (lane == 0) w_sum[warp] = fano_acc;
    __syncthreads();
    if (threadIdx.x == 0) {
        double t = 0.0;
        for (int w = 0; w < NW; w++) t += w_sum[w];   // fixed order: deterministic
        g_fano_sum[b] = t;
    }
}

// ---------------------------------------------------------------------------
// Kernel 4: final MSE and scale.
// ---------------------------------------------------------------------------
__global__ void final_kernel(const float* __restrict__ expf, float* __restrict__ out)
{
    double acc = 0.0;
    #pragma unroll
    for (int b = 0; b < NBINS; b++) {
        double fm = g_fano_sum[b] / (double)NS;
        double d  = (double)expf[b] - fm;
        acc += d * d;
    }
    out[0] = (float)(10.0 * acc / (double)NBINS);
}

extern "C" void kernel_launch(void* const* d_in, const int* in_sizes, int n_in,
                              void* d_out, int out_size)
{
    const float* spikes = (const float*)d_in[0];   // (8,600,30000) f32
    const float* expf   = (const float*)d_in[1];   // (16,) f32
    const int*   trials = (const int*)d_in[2];     // (50,) i32
    const void*  ids    = d_in[3];                 // (50,200) i32 OR i64 (detected)
    const float* mask   = (const float*)d_in[4];   // (50,200) f32

    prep_kernel<<<1, 256>>>(ids, mask);
    gather_kernel<<<dim3(NS, TCH, JSPLIT), 256>>>(spikes, trials);
    reduce_kernel<<<(NS * TQ + 255) / 256, 256>>>();
    fano_kernel<<<NBINS, 256>>>();
    final_kernel<<<1, 1>>>(expf, (float*)d_out);
}

// round 12
// speedup vs baseline: 1.6857x; 1.6857x over previous
#include <cuda_runtime.h>

// Problem constants (from reference):
//   spikes: (8, 600, 30000) f32; window t in [0, 500)
//   50 samples, up to 200 ids each, prefix mask (count in [15,200])
//   16 fano bin sizes, output = 10 * mse (scalar f32)
// NOTE: sample_ids is declared int64 in the reference but JAX demotes to
// int32 unless x64 is enabled -> detect the real dtype at runtime.
#define NS      50
#define MAXC    200
#define TQ      500        // T_END - T_START
#define NT_TOT  600
#define NN      30000
#define NBINS   16
#define JSPLIT  8          // split id-list 8 ways -> 8 partial sel buffers
#define TCH     2          // t-chunks per sample
#define TPC     250        // timesteps per chunk (500/2)
#define EPS_D   1e-7

__device__ int    g_ids[NS * MAXC];          // ids converted to int32
__device__ int    g_cnt[NS];                 // per-sample valid prefix count
__device__ float  g_part[JSPLIT][NS * TQ];   // partial gather sums (each elem written once)
__device__ double g_fano_bs[NBINS * NS];     // per-(bin,sample) fano

// BIN_MS = round(1000 * logspace(-3,0,20)) for b < 0.25  -> 16 bins
__constant__ int c_bins[NBINS] = {1, 1, 2, 3, 4, 6, 9, 13, 18, 26, 38, 55, 78, 113, 162, 234};

// ---------------------------------------------------------------------------
// Kernel 0: detect id dtype (i32 vs i64), convert to int32, compute counts.
// Detection: interpret buffer as i64, test 8 words against [0, NN). True-i64
// always passes; i32 packed two-per-word has a nonzero high half w.p. ~1.
// Deterministic for fixed inputs.
// ---------------------------------------------------------------------------
__global__ void prep_kernel(const void* __restrict__ ids_raw,
                            const float* __restrict__ mask)
{
    __shared__ int s_is64;
    const int tid = threadIdx.x;

    if (tid == 0) {
        const long long* p64 = (const long long*)ids_raw;
        int is64 = 1;
        #pragma unroll
        for (int k = 0; k < 8; k++) {
            long long v = p64[k];
            if (v < 0 || v >= NN) is64 = 0;
        }
        s_is64 = is64;
    }
    __syncthreads();

    if (s_is64) {
        const long long* p64 = (const long long*)ids_raw;
        for (int i = tid; i < NS * MAXC; i += blockDim.x)
            g_ids[i] = (int)p64[i];
    } else {
        const int* p32 = (const int*)ids_raw;
        for (int i = tid; i < NS * MAXC; i += blockDim.x)
            g_ids[i] = p32[i];
    }

    if (tid < NS) {
        int c = 0;
        for (int j = 0; j < MAXC; j++)
            if (mask[tid * MAXC + j] > 0.5f) c++;
        g_cnt[tid] = c;
    }
}

// ---------------------------------------------------------------------------
// Kernel 1: gather-sum. grid = (sample, t-chunk, j-split), block = 256.
// 800 blocks / 6400 warps -> ~43 warps/SM; each thread owns one timestep and
// walks its j-slice (~9 ids) with 8 independent accumulators for MLP.
// ---------------------------------------------------------------------------
__global__ void gather_kernel(const float* __restrict__ spikes,
                              const int* __restrict__ trials)
{
    __shared__ int sid[MAXC];

    const int s   = blockIdx.x;
    const int tid = threadIdx.x;

    if (tid < MAXC) sid[tid] = g_ids[s * MAXC + tid];
    __syncthreads();

    const int cnt  = g_cnt[s];              // mask is a prefix: valid ids are [0, cnt)
    const int jlen = (cnt + JSPLIT - 1) / JSPLIT;
    const int j0   = blockIdx.z * jlen;
    const int j1   = min(cnt, j0 + jlen);

    if (tid >= TPC) return;
    const int t     = blockIdx.y * TPC + tid;
    const int trial = trials[s];
    const float* __restrict__ p =
        spikes + (size_t)trial * NT_TOT * NN + (size_t)t * NN;

    float a0 = 0.f, a1 = 0.f, a2 = 0.f, a3 = 0.f;
    float a4 = 0.f, a5 = 0.f, a6 = 0.f, a7 = 0.f;
    int j = j0;
    for (; j + 8 <= j1; j += 8) {
        a0 += __ldg(p + sid[j + 0]);
        a1 += __ldg(p + sid[j + 1]);
        a2 += __ldg(p + sid[j + 2]);
        a3 += __ldg(p + sid[j + 3]);
        a4 += __ldg(p + sid[j + 4]);
        a5 += __ldg(p + sid[j + 5]);
        a6 += __ldg(p + sid[j + 6]);
        a7 += __ldg(p + sid[j + 7]);
    }
    for (; j < j1; j++) a0 += __ldg(p + sid[j]);

    g_part[blockIdx.z][s * TQ + t] = ((a0 + a1) + (a2 + a3)) + ((a4 + a5) + (a6 + a7));
}

// ---------------------------------------------------------------------------
// Kernel 2 (fused reduce + fano): grid = 50 samples, block = 256 (8 warps).
// Stage the sample's sel row (500 floats) in shared from the 8 partials,
// then warp w computes bins w and w+8: lanes stripe the nb bins, shuffle-
// reduce in double, lane 0 writes fano[b][s]. All shared-resident -> no
// global dependent-load chains (this was 55 us before).
// ---------------------------------------------------------------------------
__global__ void fano_kernel()
{
    __shared__ float row[TQ];

    const int s    = blockIdx.x;
    const int tid  = threadIdx.x;
    const int warp = tid >> 5;
    const int lane = tid & 31;

    for (int i = tid; i < TQ; i += blockDim.x) {
        const int o = s * TQ + i;
        row[i] = (((g_part[0][o] + g_part[1][o]) + (g_part[2][o] + g_part[3][o])) +
                  ((g_part[4][o] + g_part[5][o]) + (g_part[6][o] + g_part[7][o])));
    }
    __syncthreads();

    #pragma unroll
    for (int bb = 0; bb < 2; bb++) {
        const int b  = warp + bb * 8;
        const int bs = c_bins[b];
        const int nb = TQ / bs;             // floor division, matches reference

        double sum = 0.0, sumsq = 0.0;
        for (int i = lane; i < nb; i += 32) {
            float c = 0.f;
            const int base = i * bs;
            for (int k = 0; k < bs; k++) c += row[base + k];
            sum   += (double)c;
            sumsq += (double)c * (double)c;
        }
        #pragma unroll
        for (int off = 16; off; off >>= 1) {
            sum   += __shfl_down_sync(0xffffffffu, sum,   off);
            sumsq += __shfl_down_sync(0xffffffffu, sumsq, off);
        }
        if (lane == 0) {
            double mean = sum / (double)nb;
            double var  = sumsq / (double)nb - mean * mean;
            double m    = mean > EPS_D ? mean : EPS_D;
            g_fano_bs[b * NS + s] = var / m;
        }
    }
}

// ---------------------------------------------------------------------------
// Kernel 3: final. 16 warps, warp b reduces fano[b][:] over samples
// (deterministic shuffle tree), thread 0 computes the MSE.
// ---------------------------------------------------------------------------
__global__ void final_kernel(const float* __restrict__ expf, float* __restrict__ out)
{
    __shared__ double w_fm[NBINS];

    const int warp = threadIdx.x >> 5;
    const int lane = threadIdx.x & 31;

    double acc = 0.0;
    for (int i = lane; i < NS; i += 32) acc += g_fano_bs[warp * NS + i];
    #pragma unroll
    for (int off = 16; off; off >>= 1)
        acc += __shfl_down_sync(0xffffffffu, acc, off);
    if (lane == 0) w_fm[warp] = acc / (double)NS;
    __syncthreads();

    if (threadIdx.x == 0) {
        double mse = 0.0;
        #pragma unroll
        for (int b = 0; b < NBINS; b++) {
            double d = (double)expf[b] - w_fm[b];
            mse += d * d;
        }
        out[0] = (float)(10.0 * mse / (double)NBINS);
    }
}

extern "C" void kernel_launch(void* const* d_in, const int* in_sizes, int n_in,
                              void* d_out, int out_size)
{
    const float* spikes = (const float*)d_in[0];   // (8,600,30000) f32
    const float* expf   = (const float*)d_in[1];   // (16,) f32
    const int*   trials = (const int*)d_in[2];     // (50,) i32
    const void*  ids    = d_in[3];                 // (50,200) i32 OR i64 (detected)
    const float* mask   = (const float*)d_in[4];   // (50,200) f32

    prep_kernel<<<1, 256>>>(ids, mask);
    gather_kernel<<<dim3(NS, TCH, JSPLIT), 256>>>(spikes, trials);
    fano_kernel<<<NS, 256>>>();
    final_kernel<<<NBINS * 32 / 32, NBINS * 32>>>(expf, (float*)d_out);
}